// round 15
// baseline (speedup 1.0000x reference)
#include <cuda_runtime.h>

#define MQ 32
#define NG 256
#define DD 128
#define QH 16
#define NPAIRJOB 496   // C(32,2) quad-pair jobs

__device__ __forceinline__ unsigned long long pack2(float lo, float hi) {
    unsigned long long r;
    asm("mov.b64 %0, {%1, %2};" : "=l"(r) : "f"(lo), "f"(hi));
    return r;
}
__device__ __forceinline__ unsigned long long fma2(unsigned long long a,
                                                   unsigned long long b,
                                                   unsigned long long c) {
    unsigned long long d;
    asm("fma.rn.f32x2 %0, %1, %2, %3;" : "=l"(d) : "l"(a), "l"(b), "l"(c));
    return d;
}
__device__ __forceinline__ void unpack2(unsigned long long v, float& lo, float& hi) {
    asm("mov.b64 {%0, %1}, %2;" : "=f"(lo), "=f"(hi) : "l"(v));
}

// Symmetry kernel (spill-free revision of R14).
// outer(u) is symmetric, so for a<b:
//   |p-M'_ab| + |p-M'_ba| = 2*max(D, |p-S|), D=|Mp_ab-Mp_ba|/2,
//   S=(Mp_ab+Mp_ba)/2+ze (precomputed per-thread constants, 32 regs).
// Thread P<496 owns quad-pair (alpha<beta). Hot loop: 2 queries per pass,
// ua2 packed on the fly (minimal live set -> fits 64-reg cap, no spills).
// Diagonal quads folded into the epilogue from shared constants.
// pen(i,j) = NE*ze + 0.5*( su^2 - smRaw - NE*ze + Sum|z'| ).
__global__ __launch_bounds__(512, 2)
void jacc_pen_kernel(const float* __restrict__ qf,
                     const float* __restrict__ x,
                     const float* __restrict__ Mp,
                     const float* __restrict__ zep,
                     float* __restrict__ out) {
    const int j     = blockIdx.x >> 1;
    const int ibase = (blockIdx.x & 1) * QH;
    const int t = threadIdx.x;
    const float ze = *zep;

    __shared__ __align__(16) float u_s[QH][DD];   // 8 KB
    __shared__ float part_s[QH][128];             // 8 KB
    __shared__ float su_s[QH], sv_s[QH];
    __shared__ float sMw_s[16];
    __shared__ __align__(16) float nMd_s[128];    // -Mp[a][a]-ze
    __shared__ float nSd_s[192];                  // -(Mp_ab+Mp_ba)/2 - ze (in-quad)
    __shared__ float Dd_s[192];                   // |Mp_ab-Mp_ba|/2      (in-quad)

    const float* __restrict__ xj = x + j * DD;

    // ---- u[i][d] = max(qf[ibase+i][d], x[j][d]) ----
    #pragma unroll
    for (int k = 0; k < (QH * DD) / 512; ++k) {
        int e = t + 512 * k;
        int i = e >> 7;
        int d = e & (DD - 1);
        u_s[i][d] = fmaxf(qf[(ibase + i) * DD + d], xj[d]);
    }

    // ---- dist0 row sums: warp w handles query w ----
    {
        int i = t >> 5;
        int l = t & 31;
        float4 q4 = *reinterpret_cast<const float4*>(qf + (ibase + i) * DD + l * 4);
        float4 x4 = *reinterpret_cast<const float4*>(xj + l * 4);
        float su = (fmaxf(q4.x, x4.x) + fmaxf(q4.y, x4.y))
                 + (fmaxf(q4.z, x4.z) + fmaxf(q4.w, x4.w));
        float sv = (fminf(q4.x, x4.x) + fminf(q4.y, x4.y))
                 + (fminf(q4.z, x4.z) + fminf(q4.w, x4.w));
        #pragma unroll
        for (int off = 16; off >= 1; off >>= 1) {
            su += __shfl_xor_sync(0xffffffffu, su, off);
            sv += __shfl_xor_sync(0xffffffffu, sv, off);
        }
        if (l == 0) { su_s[i] = su; sv_s[i] = sv; }
    }

    // ---- Job decode + per-thread pair constants (32 regs) ----
    const bool isMain = (t < NPAIRJOB);
    int alpha = 0, beta = 1;
    unsigned long long nS2[4][2] = {{0,0},{0,0},{0,0},{0,0}};
    float Dv[4][4] = {{0}};
    float msum = 0.0f;

    if (isMain) {
        float ff = sqrtf(8.0f * (float)t + 1.0f);
        beta = (int)((1.0f + ff) * 0.5f);
        while (beta * (beta + 1) / 2 <= t) ++beta;
        while (beta * (beta - 1) / 2 > t) --beta;
        alpha = t - beta * (beta - 1) / 2;

        #pragma unroll
        for (int i = 0; i < 4; ++i) {
            float4 r = *reinterpret_cast<const float4*>(Mp + (4 * alpha + i) * DD + 4 * beta);
            float t0 = Mp[(4 * beta + 0) * DD + 4 * alpha + i];
            float t1 = Mp[(4 * beta + 1) * DD + 4 * alpha + i];
            float t2 = Mp[(4 * beta + 2) * DD + 4 * alpha + i];
            float t3 = Mp[(4 * beta + 3) * DD + 4 * alpha + i];
            float s0 = r.x + t0, s1 = r.y + t1, s2 = r.z + t2, s3 = r.w + t3;
            msum += (s0 + s1) + (s2 + s3);
            nS2[i][0] = pack2(-0.5f * s0 - ze, -0.5f * s1 - ze);
            nS2[i][1] = pack2(-0.5f * s2 - ze, -0.5f * s3 - ze);
            Dv[i][0] = 0.5f * fabsf(r.x - t0);
            Dv[i][1] = 0.5f * fabsf(r.y - t1);
            Dv[i][2] = 0.5f * fabsf(r.z - t2);
            Dv[i][3] = 0.5f * fabsf(r.w - t3);
        }
    }

    // ---- Diagonal-quad constants into shared ----
    if (t < 192) {
        const int I6[6] = {0, 0, 0, 1, 1, 2};
        const int J6[6] = {1, 2, 3, 2, 3, 3};
        int q = t / 6, pp = t % 6;
        int a = 4 * q + I6[pp], b = 4 * q + J6[pp];
        float mab = Mp[a * DD + b], mba = Mp[b * DD + a];
        nSd_s[t] = -0.5f * (mab + mba) - ze;
        Dd_s[t]  = 0.5f * fabsf(mab - mba);
        msum += mab + mba;
    }
    if (t < 128) {
        float maa = Mp[t * DD + t];
        nMd_s[t] = -maa - ze;
        msum += maa;
    }

    #pragma unroll
    for (int off = 16; off >= 1; off >>= 1)
        msum += __shfl_xor_sync(0xffffffffu, msum, off);
    if ((t & 31) == 0) sMw_s[t >> 5] = msum;

    __syncthreads();

    // ---- Hot loop: max(D, |ua*ub - S|) pair terms, 2 queries per pass ----
    const float* ua_p = &u_s[0][4 * alpha];
    const float* ub_p = &u_s[0][4 * beta];
    float* st_p = &part_s[0][t >> 2];
    #pragma unroll 1
    for (int ig = 0; ig < QH; ig += 2) {
        float w[2];
        #pragma unroll
        for (int s = 0; s < 2; ++s) {
            float4 va = *reinterpret_cast<const float4*>(ua_p + s * DD);
            ulonglong2 cb = *reinterpret_cast<const ulonglong2*>(ub_p + s * DD);

            float acc[4] = {0.0f, 0.0f, 0.0f, 0.0f};
            #pragma unroll
            for (int i = 0; i < 4; ++i) {
                float uav = (i == 0) ? va.x : (i == 1) ? va.y : (i == 2) ? va.z : va.w;
                unsigned long long ua2 = pack2(uav, uav);   // one live temp
                float lo, hi;
                unpack2(fma2(ua2, cb.x, nS2[i][0]), lo, hi);
                acc[0] += fmaxf(fabsf(lo), Dv[i][0]);   // FMNMX(alu) + FADD(fma)
                acc[1] += fmaxf(fabsf(hi), Dv[i][1]);
                unpack2(fma2(ua2, cb.y, nS2[i][1]), lo, hi);
                acc[2] += fmaxf(fabsf(lo), Dv[i][2]);
                acc[3] += fmaxf(fabsf(hi), Dv[i][3]);
            }
            w[s] = (acc[0] + acc[1]) + (acc[2] + acc[3]);
        }

        // 2 independent quad reductions (overlapping shfl chains)
        #pragma unroll
        for (int s = 0; s < 2; ++s)
            w[s] += __shfl_down_sync(0xffffffffu, w[s], 2, 4);
        #pragma unroll
        for (int s = 0; s < 2; ++s)
            w[s] += __shfl_down_sync(0xffffffffu, w[s], 1, 4);
        if ((t & 3) == 0) {
            st_p[0]   = isMain ? w[0] : 0.0f;
            st_p[128] = isMain ? w[1] : 0.0f;
        }

        ua_p += 2 * DD;
        ub_p += 2 * DD;
        st_p += 2 * 128;
    }

    __syncthreads();

    // ---- Final phase: warp w finishes query w (incl. diagonal terms) ----
    {
        const int w = t >> 5;
        const int l = t & 31;

        float sm = 0.0f;
        #pragma unroll
        for (int k = 0; k < 16; ++k) sm += sMw_s[k];

        float4 uq = *reinterpret_cast<const float4*>(&u_s[w][4 * l]);
        float uu[4] = {uq.x, uq.y, uq.z, uq.w};
        float4 md = *reinterpret_cast<const float4*>(&nMd_s[4 * l]);
        float dself = fabsf(fmaf(uu[0], uu[0], md.x))
                    + fabsf(fmaf(uu[1], uu[1], md.y))
                    + fabsf(fmaf(uu[2], uu[2], md.z))
                    + fabsf(fmaf(uu[3], uu[3], md.w));
        const int I6[6] = {0, 0, 0, 1, 1, 2};
        const int J6[6] = {1, 2, 3, 2, 3, 3};
        float dpair = 0.0f;
        #pragma unroll
        for (int pp = 0; pp < 6; ++pp) {
            float tv = fmaf(uu[I6[pp]], uu[J6[pp]], nSd_s[6 * l + pp]);
            dpair += fmaxf(fabsf(tv), Dd_s[6 * l + pp]);
        }

        float p = (part_s[w][l]      + part_s[w][l + 32])
                + (part_s[w][l + 64] + part_s[w][l + 96]);
        float tot = 2.0f * (p + dpair) + dself;   // pair terms were half-scaled
        #pragma unroll
        for (int off = 16; off >= 1; off >>= 1)
            tot += __shfl_xor_sync(0xffffffffu, tot, off);
        if (l == 0) {
            float su = su_s[w];
            const float NE = (float)(DD * DD);  // 16384
            float pen = NE * ze + 0.5f * ((su * su - sm - NE * ze) + tot);
            out[(ibase + w) * NG + j] = sv_s[w] / su - 0.001f * pen;
        }
    }
}

extern "C" void kernel_launch(void* const* d_in, const int* in_sizes, int n_in,
                              void* d_out, int out_size) {
    const float* qf = (const float*)d_in[0];   // (32, 128)
    const float* x  = (const float*)d_in[1];   // (256, 128)
    const float* Mp = (const float*)d_in[2];   // (128, 128)
    const float* ze = (const float*)d_in[3];   // scalar
    float* out = (float*)d_out;                // (32, 256)
    (void)in_sizes; (void)n_in; (void)out_size;

    jacc_pen_kernel<<<2 * NG, 512>>>(qf, x, Mp, ze, out);
}

// round 16
// speedup vs baseline: 1.0142x; 1.0142x over previous
#include <cuda_runtime.h>

#define MQ 32
#define NG 256
#define DD 128
#define QH 16
#define NPAIRJOB 496   // C(32,2) quad-pair jobs
#define NT 256

__device__ __forceinline__ unsigned long long pack2(float lo, float hi) {
    unsigned long long r;
    asm("mov.b64 %0, {%1, %2};" : "=l"(r) : "f"(lo), "f"(hi));
    return r;
}
__device__ __forceinline__ unsigned long long fma2(unsigned long long a,
                                                   unsigned long long b,
                                                   unsigned long long c) {
    unsigned long long d;
    asm("fma.rn.f32x2 %0, %1, %2, %3;" : "=l"(d) : "l"(a), "l"(b), "l"(c));
    return d;
}
__device__ __forceinline__ void unpack2(unsigned long long v, float& lo, float& hi) {
    asm("mov.b64 {%0, %1}, %2;" : "=f"(lo), "=f"(hi) : "l"(v));
}

// Symmetry kernel, 256 threads / 128-reg budget (fixes R14/R15 spills).
// outer(u) symmetric: for a<b, |p-M'_ab|+|p-M'_ba| = 2*max(D,|p-S|),
// D=|Mp_ab-Mp_ba|/2, S=(Mp_ab+Mp_ba)/2+ze. Each thread owns TWO quad-pair
// jobs (t, t+256) -> 64 regs of constants, fits the 128-reg budget.
// Diagonal quads folded into the epilogue from shared constants.
// pen(i,j) = NE*ze + 0.5*( su^2 - smRaw - NE*ze + Sum|z'| ).
__global__ __launch_bounds__(NT, 2)
void jacc_pen_kernel(const float* __restrict__ qf,
                     const float* __restrict__ x,
                     const float* __restrict__ Mp,
                     const float* __restrict__ zep,
                     float* __restrict__ out) {
    const int j     = blockIdx.x >> 1;
    const int ibase = (blockIdx.x & 1) * QH;
    const int t = threadIdx.x;
    const float ze = *zep;

    __shared__ __align__(16) float u_s[QH][DD];   // 8 KB
    __shared__ float part_s[QH][64];              // 4 KB
    __shared__ float su_s[QH], sv_s[QH];
    __shared__ float sMw_s[8];
    __shared__ __align__(16) float nMd_s[128];    // -Mp[a][a]-ze
    __shared__ float nSd_s[192];                  // -(Mp_ab+Mp_ba)/2 - ze (in-quad)
    __shared__ float Dd_s[192];                   // |Mp_ab-Mp_ba|/2      (in-quad)

    const float* __restrict__ xj = x + j * DD;

    // ---- u[i][d] = max(qf[ibase+i][d], x[j][d]) : 2048 / 256 threads ----
    #pragma unroll
    for (int k = 0; k < (QH * DD) / NT; ++k) {
        int e = t + NT * k;
        int i = e >> 7;
        int d = e & (DD - 1);
        u_s[i][d] = fmaxf(qf[(ibase + i) * DD + d], xj[d]);
    }

    // ---- dist0 row sums: 8 warps x 2 queries ----
    {
        int w = t >> 5, l = t & 31;
        #pragma unroll
        for (int r = 0; r < 2; ++r) {
            int i = w + 8 * r;
            float4 q4 = *reinterpret_cast<const float4*>(qf + (ibase + i) * DD + l * 4);
            float4 x4 = *reinterpret_cast<const float4*>(xj + l * 4);
            float su = (fmaxf(q4.x, x4.x) + fmaxf(q4.y, x4.y))
                     + (fmaxf(q4.z, x4.z) + fmaxf(q4.w, x4.w));
            float sv = (fminf(q4.x, x4.x) + fminf(q4.y, x4.y))
                     + (fminf(q4.z, x4.z) + fminf(q4.w, x4.w));
            #pragma unroll
            for (int off = 16; off >= 1; off >>= 1) {
                su += __shfl_xor_sync(0xffffffffu, su, off);
                sv += __shfl_xor_sync(0xffffffffu, sv, off);
            }
            if (l == 0) { su_s[i] = su; sv_s[i] = sv; }
        }
    }

    // ---- Two jobs per thread: decode + constants (64 regs) ----
    int alpha[2], beta[2];
    unsigned long long nS2[2][4][2];
    float Dv[2][4][4];
    float msum = 0.0f;
    const float mask1 = (t + NT < NPAIRJOB) ? 1.0f : 0.0f;

    #pragma unroll
    for (int g = 0; g < 2; ++g) {
        int job = t + g * NT;
        bool valid = (job < NPAIRJOB);
        int jb = valid ? job : 0;
        float ff = sqrtf(8.0f * (float)jb + 1.0f);
        int b = (int)((1.0f + ff) * 0.5f);
        while (b * (b + 1) / 2 <= jb) ++b;
        while (b * (b - 1) / 2 > jb) --b;
        int a = jb - b * (b - 1) / 2;
        alpha[g] = a; beta[g] = b;

        #pragma unroll
        for (int i = 0; i < 4; ++i) {
            float4 r = *reinterpret_cast<const float4*>(Mp + (4 * a + i) * DD + 4 * b);
            float t0 = Mp[(4 * b + 0) * DD + 4 * a + i];
            float t1 = Mp[(4 * b + 1) * DD + 4 * a + i];
            float t2 = Mp[(4 * b + 2) * DD + 4 * a + i];
            float t3 = Mp[(4 * b + 3) * DD + 4 * a + i];
            float s0 = r.x + t0, s1 = r.y + t1, s2 = r.z + t2, s3 = r.w + t3;
            if (valid) msum += (s0 + s1) + (s2 + s3);
            nS2[g][i][0] = pack2(-0.5f * s0 - ze, -0.5f * s1 - ze);
            nS2[g][i][1] = pack2(-0.5f * s2 - ze, -0.5f * s3 - ze);
            Dv[g][i][0] = 0.5f * fabsf(r.x - t0);
            Dv[g][i][1] = 0.5f * fabsf(r.y - t1);
            Dv[g][i][2] = 0.5f * fabsf(r.z - t2);
            Dv[g][i][3] = 0.5f * fabsf(r.w - t3);
        }
    }

    // ---- Diagonal-quad constants into shared ----
    if (t < 192) {
        const int I6[6] = {0, 0, 0, 1, 1, 2};
        const int J6[6] = {1, 2, 3, 2, 3, 3};
        int q = t / 6, pp = t % 6;
        int a = 4 * q + I6[pp], b = 4 * q + J6[pp];
        float mab = Mp[a * DD + b], mba = Mp[b * DD + a];
        nSd_s[t] = -0.5f * (mab + mba) - ze;
        Dd_s[t]  = 0.5f * fabsf(mab - mba);
        msum += mab + mba;
    }
    if (t < 128) {
        float maa = Mp[t * DD + t];
        nMd_s[t] = -maa - ze;
        msum += maa;
    }

    #pragma unroll
    for (int off = 16; off >= 1; off >>= 1)
        msum += __shfl_xor_sync(0xffffffffu, msum, off);
    if ((t & 31) == 0) sMw_s[t >> 5] = msum;

    __syncthreads();

    // ---- Hot loop: 2 jobs x max(D, |ua*ub - S|), 2 queries per pass ----
    const float* u0 = &u_s[0][0];
    float* st_p = &part_s[0][t >> 2];
    #pragma unroll 1
    for (int ig = 0; ig < QH; ig += 2) {
        float w[2];
        #pragma unroll
        for (int s = 0; s < 2; ++s) {
            const float* uq = u0 + (ig + s) * DD;
            float tsum[2];
            #pragma unroll
            for (int g = 0; g < 2; ++g) {
                float4 va = *reinterpret_cast<const float4*>(uq + 4 * alpha[g]);
                ulonglong2 cb = *reinterpret_cast<const ulonglong2*>(uq + 4 * beta[g]);
                float acc[4] = {0.0f, 0.0f, 0.0f, 0.0f};
                #pragma unroll
                for (int i = 0; i < 4; ++i) {
                    float uav = (i == 0) ? va.x : (i == 1) ? va.y
                              : (i == 2) ? va.z : va.w;
                    unsigned long long ua2 = pack2(uav, uav);
                    float lo, hi;
                    unpack2(fma2(ua2, cb.x, nS2[g][i][0]), lo, hi);
                    acc[0] += fmaxf(fabsf(lo), Dv[g][i][0]);
                    acc[1] += fmaxf(fabsf(hi), Dv[g][i][1]);
                    unpack2(fma2(ua2, cb.y, nS2[g][i][1]), lo, hi);
                    acc[2] += fmaxf(fabsf(lo), Dv[g][i][2]);
                    acc[3] += fmaxf(fabsf(hi), Dv[g][i][3]);
                }
                tsum[g] = (acc[0] + acc[1]) + (acc[2] + acc[3]);
            }
            w[s] = fmaf(mask1, tsum[1], tsum[0]);   // mask dummy job1
        }

        // 2 independent quad reductions
        #pragma unroll
        for (int s = 0; s < 2; ++s)
            w[s] += __shfl_down_sync(0xffffffffu, w[s], 2, 4);
        #pragma unroll
        for (int s = 0; s < 2; ++s)
            w[s] += __shfl_down_sync(0xffffffffu, w[s], 1, 4);
        if ((t & 3) == 0) {
            st_p[0]  = w[0];
            st_p[64] = w[1];
        }
        st_p += 2 * 64;
    }

    __syncthreads();

    // ---- Final phase: 8 warps x 2 queries (incl. diagonal terms) ----
    {
        const int w = t >> 5;
        const int l = t & 31;

        float sm = ((sMw_s[0] + sMw_s[1]) + (sMw_s[2] + sMw_s[3]))
                 + ((sMw_s[4] + sMw_s[5]) + (sMw_s[6] + sMw_s[7]));

        const int I6[6] = {0, 0, 0, 1, 1, 2};
        const int J6[6] = {1, 2, 3, 2, 3, 3};
        #pragma unroll
        for (int r = 0; r < 2; ++r) {
            int q = w + 8 * r;
            float4 uq = *reinterpret_cast<const float4*>(&u_s[q][4 * l]);
            float uu[4] = {uq.x, uq.y, uq.z, uq.w};
            float4 md = *reinterpret_cast<const float4*>(&nMd_s[4 * l]);
            float dself = fabsf(fmaf(uu[0], uu[0], md.x))
                        + fabsf(fmaf(uu[1], uu[1], md.y))
                        + fabsf(fmaf(uu[2], uu[2], md.z))
                        + fabsf(fmaf(uu[3], uu[3], md.w));
            float dpair = 0.0f;
            #pragma unroll
            for (int pp = 0; pp < 6; ++pp) {
                float tv = fmaf(uu[I6[pp]], uu[J6[pp]], nSd_s[6 * l + pp]);
                dpair += fmaxf(fabsf(tv), Dd_s[6 * l + pp]);
            }

            float p = part_s[q][l] + part_s[q][l + 32];
            float tot = 2.0f * (p + dpair) + dself;   // pair terms half-scaled
            #pragma unroll
            for (int off = 16; off >= 1; off >>= 1)
                tot += __shfl_xor_sync(0xffffffffu, tot, off);
            if (l == 0) {
                float su = su_s[q];
                const float NE = (float)(DD * DD);  // 16384
                float pen = NE * ze + 0.5f * ((su * su - sm - NE * ze) + tot);
                out[(ibase + q) * NG + j] = sv_s[q] / su - 0.001f * pen;
            }
        }
    }
}

extern "C" void kernel_launch(void* const* d_in, const int* in_sizes, int n_in,
                              void* d_out, int out_size) {
    const float* qf = (const float*)d_in[0];   // (32, 128)
    const float* x  = (const float*)d_in[1];   // (256, 128)
    const float* Mp = (const float*)d_in[2];   // (128, 128)
    const float* ze = (const float*)d_in[3];   // scalar
    float* out = (float*)d_out;                // (32, 256)
    (void)in_sizes; (void)n_in; (void)out_size;

    jacc_pen_kernel<<<2 * NG, NT>>>(qf, x, Mp, ze, out);
}

// round 17
// speedup vs baseline: 1.1149x; 1.0993x over previous
#include <cuda_runtime.h>

#define MQ 32
#define NG 256
#define DD 128
#define QH 16   // queries per block

// Block = (gallery item j, query half): grid 512 x 512 threads.
// Thread owns a-rows (t>>4)*4..+3 and b-cols {4m..4m+3, 64+4m..64+4m+3}
// (conflict-free LDS.128). Hot loop is PURE C (fmaf + fabsf) — no inline asm,
// so ptxas owns register allocation (eliminates pack/unpack MOV bloat).
// pen(i,j) = 16384*ze + 0.5*( su_i^2 - sumMp - 16384*ze + sum|t'| ),
// t' = ua*ub - Mp - ze.
__global__ __launch_bounds__(512, 2)
void jacc_pen_kernel(const float* __restrict__ qf,
                     const float* __restrict__ x,
                     const float* __restrict__ Mp,
                     const float* __restrict__ zep,
                     float* __restrict__ out) {
    const int j     = blockIdx.x >> 1;
    const int ibase = (blockIdx.x & 1) * QH;
    const int t = threadIdx.x;
    const float ze = *zep;

    __shared__ __align__(16) float u_s[QH][DD];   // 8 KB
    __shared__ float part_s[QH][128];             // 8 KB
    __shared__ float su_s[QH], sv_s[QH];
    __shared__ float sMw_s[16];

    const float* __restrict__ xj = x + j * DD;

    // ---- u[i][d] = max(qf[ibase+i][d], x[j][d]) ----
    #pragma unroll
    for (int k = 0; k < (QH * DD) / 512; ++k) {
        int e = t + 512 * k;
        int i = e >> 7;
        int d = e & (DD - 1);
        u_s[i][d] = fmaxf(qf[(ibase + i) * DD + d], xj[d]);
    }

    // ---- dist0 row sums: warp w handles query w ----
    {
        int i = t >> 5;
        int l = t & 31;
        float4 q4 = *reinterpret_cast<const float4*>(qf + (ibase + i) * DD + l * 4);
        float4 x4 = *reinterpret_cast<const float4*>(xj + l * 4);
        float su = (fmaxf(q4.x, x4.x) + fmaxf(q4.y, x4.y))
                 + (fmaxf(q4.z, x4.z) + fmaxf(q4.w, x4.w));
        float sv = (fminf(q4.x, x4.x) + fminf(q4.y, x4.y))
                 + (fminf(q4.z, x4.z) + fminf(q4.w, x4.w));
        #pragma unroll
        for (int off = 16; off >= 1; off >>= 1) {
            su += __shfl_xor_sync(0xffffffffu, su, off);
            sv += __shfl_xor_sync(0xffffffffu, sv, off);
        }
        if (l == 0) { su_s[i] = su; sv_s[i] = sv; }
    }

    // ---- Load 4x8 Mp tile as scalars (-Mp - ze); warp-reduce tile sum ----
    const int a0 = (t >> 4) * 4;
    const int m  = t & 15;
    const int bA = 4 * m;
    const int bB = 64 + 4 * m;
    float nM[4][8];
    {
        float msum = 0.0f;
        #pragma unroll
        for (int aa = 0; aa < 4; ++aa) {
            float4 m0 = *reinterpret_cast<const float4*>(Mp + (a0 + aa) * DD + bA);
            float4 m1 = *reinterpret_cast<const float4*>(Mp + (a0 + aa) * DD + bB);
            msum += ((m0.x + m0.y) + (m0.z + m0.w)) + ((m1.x + m1.y) + (m1.z + m1.w));
            nM[aa][0] = -m0.x - ze; nM[aa][1] = -m0.y - ze;
            nM[aa][2] = -m0.z - ze; nM[aa][3] = -m0.w - ze;
            nM[aa][4] = -m1.x - ze; nM[aa][5] = -m1.y - ze;
            nM[aa][6] = -m1.z - ze; nM[aa][7] = -m1.w - ze;
        }
        #pragma unroll
        for (int off = 16; off >= 1; off >>= 1)
            msum += __shfl_xor_sync(0xffffffffu, msum, off);
        if ((t & 31) == 0) sMw_s[t >> 5] = msum;
    }

    __syncthreads();

    // ---- Hot loop: sum |ua*ub - Mp - ze| over the 4x8 tile, per query ----
    const float* ua_p = &u_s[0][a0];
    const float* ub_p = &u_s[0][bA];
    float* st_p = &part_s[0][t >> 2];
    #pragma unroll 1
    for (int i = 0; i < QH; ++i) {
        float4 va = *reinterpret_cast<const float4*>(ua_p);
        float4 b0 = *reinterpret_cast<const float4*>(ub_p);
        float4 b1 = *reinterpret_cast<const float4*>(ub_p + 64);
        float ua[4] = {va.x, va.y, va.z, va.w};
        float ub[8] = {b0.x, b0.y, b0.z, b0.w, b1.x, b1.y, b1.z, b1.w};

        float acc[4] = {0.0f, 0.0f, 0.0f, 0.0f};
        #pragma unroll
        for (int aa = 0; aa < 4; ++aa) {
            #pragma unroll
            for (int bb = 0; bb < 8; ++bb) {
                float tv = fmaf(ua[aa], ub[bb], nM[aa][bb]);
                acc[bb & 3] += fabsf(tv);      // FADD with |src| modifier
            }
        }
        float w = (acc[0] + acc[1]) + (acc[2] + acc[3]);

        // quad reduce (2 shfl), predicated STS
        w += __shfl_down_sync(0xffffffffu, w, 2, 4);
        w += __shfl_down_sync(0xffffffffu, w, 1, 4);
        if ((t & 3) == 0) *st_p = w;

        ua_p += DD;
        ub_p += DD;
        st_p += 128;
    }

    __syncthreads();

    // ---- Final phase: warp w finishes query w ----
    {
        const int w = t >> 5;
        const int l = t & 31;

        float sm = 0.0f;
        #pragma unroll
        for (int k = 0; k < 16; ++k) sm += sMw_s[k];

        float p = (part_s[w][l]      + part_s[w][l + 32])
                + (part_s[w][l + 64] + part_s[w][l + 96]);
        #pragma unroll
        for (int off = 16; off >= 1; off >>= 1)
            p += __shfl_xor_sync(0xffffffffu, p, off);
        if (l == 0) {
            float su = su_s[w];
            const float NE = (float)(DD * DD);  // 16384
            float pen = NE * ze + 0.5f * ((su * su - sm - NE * ze) + p);
            out[(ibase + w) * NG + j] = sv_s[w] / su - 0.001f * pen;
        }
    }
}

extern "C" void kernel_launch(void* const* d_in, const int* in_sizes, int n_in,
                              void* d_out, int out_size) {
    const float* qf = (const float*)d_in[0];   // (32, 128)
    const float* x  = (const float*)d_in[1];   // (256, 128)
    const float* Mp = (const float*)d_in[2];   // (128, 128)
    const float* ze = (const float*)d_in[3];   // scalar
    float* out = (float*)d_out;                // (32, 256)
    (void)in_sizes; (void)n_in; (void)out_size;

    jacc_pen_kernel<<<2 * NG, 512>>>(qf, x, Mp, ze, out);
}